// round 1
// baseline (speedup 1.0000x reference)
#include <cuda_runtime.h>
#include <cuda_bf16.h>
#include <cstdint>

// ---------------- problem constants (fixed shapes) ----------------
constexpr int B = 4, T = 2048, C = 1024, H = 16, D = 64;
constexpr int BT = B * T;              // 8192 rows
constexpr int NC = 32;                 // scan chunks
constexpr int L  = T / NC;             // 64 steps per chunk

// ---------------- scratch (static device globals; no allocs) ------
__device__ float g_xk[BT * C];
__device__ float g_xv[BT * C];
__device__ float g_xr[BT * C];
__device__ float g_k [BT * C];   // k, then overwritten with exp(k)
__device__ float g_v [BT * C];
__device__ float g_r [BT * C];
__device__ float g_rwkv[BT * C];
__device__ float g_S [B * H * T];          // per-(b,h,t) sum_d exp(k)
__device__ float g_cA[B * H * NC * D];     // chunk end-state sa
__device__ float g_cB[B * H * NC];         // chunk end-state sb
__device__ float g_iA[B * H * NC * D];     // chunk carry-in sa
__device__ float g_iB[B * H * NC];         // chunk carry-in sb

// ---------------- f32x2 packed helpers ----------------------------
typedef unsigned long long u64;

__device__ __forceinline__ u64 pk2(float lo, float hi) {
    u64 r;
    asm("mov.b64 %0, {%1, %2};" : "=l"(r) : "f"(lo), "f"(hi));
    return r;
}
__device__ __forceinline__ void upk2(u64 v, float &lo, float &hi) {
    asm("mov.b64 {%0, %1}, %2;" : "=f"(lo), "=f"(hi) : "l"(v));
}
__device__ __forceinline__ u64 ffma2(u64 a, u64 b, u64 c) {
    u64 d;
    asm("fma.rn.f32x2 %0, %1, %2, %3;" : "=l"(d) : "l"(a), "l"(b), "l"(c));
    return d;
}

// ---------------- kernel 1: token-shift mix ------------------------
// xk = x*mk + x_prev*(1-mk)  (same for v, r); x_prev is x shifted by one t.
__global__ void mix_kernel(const float* __restrict__ x,
                           const float* __restrict__ mk,
                           const float* __restrict__ mv,
                           const float* __restrict__ mr) {
    int i = blockIdx.x * blockDim.x + threadIdx.x;   // float4 index
    int e = i * 4;
    int c   = e & (C - 1);
    int row = e >> 10;             // / C
    int t   = row & (T - 1);

    float4 xc = *(const float4*)(x + e);
    float4 xp = make_float4(0.f, 0.f, 0.f, 0.f);
    if (t > 0) xp = *(const float4*)(x + e - C);

    float4 a = *(const float4*)(mk + c);
    float4 b = *(const float4*)(mv + c);
    float4 d = *(const float4*)(mr + c);

    float4 ok, ov, orr;
    ok.x = xc.x*a.x + xp.x*(1.f-a.x);  ok.y = xc.y*a.y + xp.y*(1.f-a.y);
    ok.z = xc.z*a.z + xp.z*(1.f-a.z);  ok.w = xc.w*a.w + xp.w*(1.f-a.w);
    ov.x = xc.x*b.x + xp.x*(1.f-b.x);  ov.y = xc.y*b.y + xp.y*(1.f-b.y);
    ov.z = xc.z*b.z + xp.z*(1.f-b.z);  ov.w = xc.w*b.w + xp.w*(1.f-b.w);
    orr.x = xc.x*d.x + xp.x*(1.f-d.x); orr.y = xc.y*d.y + xp.y*(1.f-d.y);
    orr.z = xc.z*d.z + xp.z*(1.f-d.z); orr.w = xc.w*d.w + xp.w*(1.f-d.w);

    *(float4*)(g_xk + e) = ok;
    *(float4*)(g_xv + e) = ov;
    *(float4*)(g_xr + e) = orr;
}

// ---------------- kernel 2: SGEMM (TN, f32x2 packed FMA) -----------
// Cmat[m][n] = sum_k A[m][k] * W[n][k].  128x128x8 tile, 256 threads,
// 8x8 per thread with packed fma.rn.f32x2 accumulators.
// EPI: 0 = none, 1 = sigmoid.
template<int EPI>
__global__ __launch_bounds__(256, 2)
void sgemm_tn(const float* __restrict__ A, const float* __restrict__ W,
              float* __restrict__ Cmat, int M, int N, int K) {
    __shared__ __align__(16) float As[8][128];
    __shared__ __align__(16) float Bs[8][128];

    const int tid = threadIdx.x;
    const int bm = blockIdx.y << 7;
    const int bn = blockIdx.x << 7;

    const int lrow = tid >> 1;            // 0..127
    const int lcol = (tid & 1) << 2;      // 0 or 4
    const float* Ap = A + (size_t)(bm + lrow) * K + lcol;
    const float* Wp = W + (size_t)(bn + lrow) * K + lcol;

    const int nB = (tid & 15) << 3;       // 0..120
    const int mB = (tid >> 4) << 3;       // 0..120

    u64 acc[8][4];
#pragma unroll
    for (int i = 0; i < 8; i++)
#pragma unroll
        for (int j = 0; j < 4; j++) acc[i][j] = 0ull;

    float4 a4 = *(const float4*)Ap;
    float4 w4 = *(const float4*)Wp;

    for (int kk = 0; kk < K; kk += 8) {
        __syncthreads();
        As[lcol+0][lrow] = a4.x; As[lcol+1][lrow] = a4.y;
        As[lcol+2][lrow] = a4.z; As[lcol+3][lrow] = a4.w;
        Bs[lcol+0][lrow] = w4.x; Bs[lcol+1][lrow] = w4.y;
        Bs[lcol+2][lrow] = w4.z; Bs[lcol+3][lrow] = w4.w;
        __syncthreads();

        if (kk + 8 < K) {                 // register prefetch of next tile
            a4 = *(const float4*)(Ap + kk + 8);
            w4 = *(const float4*)(Wp + kk + 8);
        }

#pragma unroll
        for (int k = 0; k < 8; k++) {
            const float4 am0 = *(const float4*)&As[k][mB];
            const float4 am1 = *(const float4*)&As[k][mB + 4];
            const ulonglong2 b0 = *(const ulonglong2*)&Bs[k][nB];
            const ulonglong2 b1 = *(const ulonglong2*)&Bs[k][nB + 4];
            float av[8] = {am0.x, am0.y, am0.z, am0.w,
                           am1.x, am1.y, am1.z, am1.w};
#pragma unroll
            for (int i = 0; i < 8; i++) {
                u64 ad = pk2(av[i], av[i]);
                acc[i][0] = ffma2(ad, b0.x, acc[i][0]);
                acc[i][1] = ffma2(ad, b0.y, acc[i][1]);
                acc[i][2] = ffma2(ad, b1.x, acc[i][2]);
                acc[i][3] = ffma2(ad, b1.y, acc[i][3]);
            }
        }
    }

#pragma unroll
    for (int i = 0; i < 8; i++) {
        float o[8];
        upk2(acc[i][0], o[0], o[1]); upk2(acc[i][1], o[2], o[3]);
        upk2(acc[i][2], o[4], o[5]); upk2(acc[i][3], o[6], o[7]);
        if (EPI == 1) {
#pragma unroll
            for (int j = 0; j < 8; j++) o[j] = 1.f / (1.f + __expf(-o[j]));
        }
        float* cp = Cmat + (size_t)(bm + mB + i) * N + bn + nB;
        *(float4*)cp       = make_float4(o[0], o[1], o[2], o[3]);
        *(float4*)(cp + 4) = make_float4(o[4], o[5], o[6], o[7]);
    }
}

// ---------------- kernel 3: ek = exp(k) in-place + row sums S ------
__global__ void ekS_kernel() {
    int w    = (blockIdx.x * blockDim.x + threadIdx.x) >> 5;  // (b,t,h) row
    int lane = threadIdx.x & 31;
    int h  = w & (H - 1);
    int bt = w >> 4;                       // b*T + t
    size_t base = (size_t)bt * C + h * D + lane * 2;

    float2 kv = *(float2*)(g_k + base);
    float e0 = __expf(kv.x), e1 = __expf(kv.y);
    *(float2*)(g_k + base) = make_float2(e0, e1);

    float s = e0 + e1;
#pragma unroll
    for (int o = 16; o; o >>= 1) s += __shfl_xor_sync(0xffffffffu, s, o);
    if (lane == 0) {
        int b = bt >> 11;                  // / T
        int t = bt & (T - 1);
        g_S[(size_t)(b * H + h) * T + t] = s;
    }
}

// ---------------- kernel 4: chunk scan pass 1 (end states) ---------
__global__ void scan1_kernel(const float* __restrict__ td) {
    int w    = (blockIdx.x * blockDim.x + threadIdx.x) >> 5;  // (bh, chunk)
    int lane = threadIdx.x & 31;
    int chunk = w & (NC - 1);
    int bh    = w >> 5;                    // NC = 32
    int h = bh & (H - 1);
    int b = bh >> 4;

    float ew = __expf(-__expf(td[h]));
    int t0 = chunk * L;
    size_t base = (size_t)(b * T + t0) * C + h * D + lane * 2;
    const float* Sp = g_S + (size_t)bh * T + t0;

    float sax = 0.f, say = 0.f, sb = 0.f;
#pragma unroll 4
    for (int s = 0; s < L; s++) {
        float2 e  = *(const float2*)(g_k + base);
        float2 vv = *(const float2*)(g_v + base);
        sax = ew * sax + e.x * vv.x;
        say = ew * say + e.y * vv.y;
        sb  = ew * sb  + Sp[s];
        base += C;
    }
    size_t ci = (size_t)w * D + lane * 2;
    g_cA[ci] = sax; g_cA[ci + 1] = say;
    if (lane == 0) g_cB[w] = sb;
}

// ---------------- kernel 5: sequential carry combine ---------------
__global__ void combine_kernel(const float* __restrict__ td) {
    int bh   = blockIdx.x;                 // 64 blocks of 32 threads
    int lane = threadIdx.x;
    int h = bh & (H - 1);
    float ewL = __expf(-(float)L * __expf(td[h]));

    float cax = 0.f, cay = 0.f, cb = 0.f;
    for (int c = 0; c < NC; c++) {
        size_t w  = (size_t)bh * NC + c;
        size_t ci = w * D + lane * 2;
        float Ax = g_cA[ci], Ay = g_cA[ci + 1];
        float Bc = g_cB[w];
        g_iA[ci] = cax; g_iA[ci + 1] = cay;
        if (lane == 0) g_iB[w] = cb;
        cax = ewL * cax + Ax;
        cay = ewL * cay + Ay;
        cb  = ewL * cb  + Bc;
    }
}

// ---------------- kernel 6: scan pass 2 (outputs, fused r*) --------
__global__ void scan3_kernel(const float* __restrict__ td,
                             const float* __restrict__ tf) {
    int w    = (blockIdx.x * blockDim.x + threadIdx.x) >> 5;
    int lane = threadIdx.x & 31;
    int chunk = w & (NC - 1);
    int bh    = w >> 5;
    int h = bh & (H - 1);
    int b = bh >> 4;

    float ew = __expf(-__expf(td[h]));
    float Eu = __expf(tf[h]);
    int t0 = chunk * L;
    size_t base = (size_t)(b * T + t0) * C + h * D + lane * 2;
    const float* Sp = g_S + (size_t)bh * T + t0;

    size_t ci = (size_t)w * D + lane * 2;
    float sax = g_iA[ci], say = g_iA[ci + 1];
    float sb  = g_iB[w];

#pragma unroll 4
    for (int s = 0; s < L; s++) {
        float2 e  = *(const float2*)(g_k + base);
        float2 vv = *(const float2*)(g_v + base);
        float2 r2 = *(const float2*)(g_r + base);
        float Sv = Sp[s];

        float den = sb + fmaxf(Eu * Sv, 1e-6f);
        float inv = 1.0f / den;
        float nx = sax + Eu * e.x * vv.x;
        float ny = say + Eu * e.y * vv.y;
        float2 o;
        o.x = r2.x * (nx * inv);
        o.y = r2.y * (ny * inv);
        *(float2*)(g_rwkv + base) = o;

        sax = ew * sax + e.x * vv.x;
        say = ew * say + e.y * vv.y;
        sb  = ew * sb  + Sv;
        base += C;
    }
}

// ---------------- launch ------------------------------------------
extern "C" void kernel_launch(void* const* d_in, const int* in_sizes, int n_in,
                              void* d_out, int out_size) {
    const float* x  = (const float*)d_in[0];
    const float* mk = (const float*)d_in[1];
    const float* mv = (const float*)d_in[2];
    const float* mr = (const float*)d_in[3];
    const float* Wk = (const float*)d_in[4];
    const float* Wv = (const float*)d_in[5];
    const float* Wr = (const float*)d_in[6];
    const float* Wo = (const float*)d_in[7];
    const float* td = (const float*)d_in[8];
    const float* tf = (const float*)d_in[9];
    float* out = (float*)d_out;

    float *p_xk, *p_xv, *p_xr, *p_k, *p_v, *p_r, *p_rwkv;
    cudaGetSymbolAddress((void**)&p_xk,   g_xk);
    cudaGetSymbolAddress((void**)&p_xv,   g_xv);
    cudaGetSymbolAddress((void**)&p_xr,   g_xr);
    cudaGetSymbolAddress((void**)&p_k,    g_k);
    cudaGetSymbolAddress((void**)&p_v,    g_v);
    cudaGetSymbolAddress((void**)&p_r,    g_r);
    cudaGetSymbolAddress((void**)&p_rwkv, g_rwkv);

    // 1) token-shift mix
    mix_kernel<<<(BT * C / 4) / 256, 256>>>(x, mk, mv, mr);

    // 2) projections: k, v, r(sigmoid)
    dim3 gg(C / 128, BT / 128);   // (8, 64)
    sgemm_tn<0><<<gg, 256>>>(p_xk, Wk, p_k, BT, C, C);
    sgemm_tn<0><<<gg, 256>>>(p_xv, Wv, p_v, BT, C, C);
    sgemm_tn<1><<<gg, 256>>>(p_xr, Wr, p_r, BT, C, C);

    // 3) exp(k) in-place + head row-sums S
    ekS_kernel<<<(B * T * H * 32) / 256, 256>>>();

    // 4-6) chunked linear scan
    scan1_kernel<<<(B * H * NC * 32) / 256, 256>>>(td);
    combine_kernel<<<B * H, 32>>>(td);
    scan3_kernel<<<(B * H * NC * 32) / 256, 256>>>(td, tf);

    // 7) output projection
    sgemm_tn<0><<<gg, 256>>>(p_rwkv, Wo, out, BT, C, C);
}

// round 5
// speedup vs baseline: 2.4554x; 2.4554x over previous
#include <cuda_runtime.h>
#include <cuda_bf16.h>
#include <cstdint>

// ---------------- problem constants ----------------
constexpr int B = 4, T = 2048, C = 1024, H = 16, D = 64;
constexpr int BT = B * T;              // 8192 rows
constexpr int NC = 32;                 // scan chunks
constexpr int L  = T / NC;             // 64 steps per chunk

// ---------------- scratch (static device globals) ----------------
__device__ __nv_bfloat16 g_xkh[BT * C], g_xkl[BT * C];
__device__ __nv_bfloat16 g_xvh[BT * C], g_xvl[BT * C];
__device__ __nv_bfloat16 g_xrh[BT * C], g_xrl[BT * C];
__device__ __nv_bfloat16 g_Wh[4 * C * C], g_Wl[4 * C * C];   // Wk,Wv,Wr,Wo
__device__ float g_k[BT * C];    // k, then exp(k)
__device__ float g_v[BT * C];
__device__ float g_r[BT * C];
__device__ __nv_bfloat16 g_rwh[BT * C], g_rwl[BT * C];
__device__ float g_S [B * H * T];
__device__ float g_cA[B * H * NC * D];
__device__ float g_cB[B * H * NC];
__device__ float g_iA[B * H * NC * D];
__device__ float g_iB[B * H * NC];

// ---------------- helpers ----------------------------------------
__device__ __forceinline__ uint32_t s2u(const void* p) {
    uint32_t a;
    asm("{ .reg .u64 t; cvta.to.shared.u64 t, %1; cvt.u32.u64 %0, t; }"
        : "=r"(a) : "l"(p));
    return a;
}

__device__ __forceinline__ void mma_bf16(float c[4],
                                         uint32_t a0, uint32_t a1, uint32_t a2, uint32_t a3,
                                         uint32_t b0, uint32_t b1) {
    asm volatile(
        "mma.sync.aligned.m16n8k16.row.col.f32.bf16.bf16.f32 "
        "{%0,%1,%2,%3}, {%4,%5,%6,%7}, {%8,%9}, {%0,%1,%2,%3};"
        : "+f"(c[0]), "+f"(c[1]), "+f"(c[2]), "+f"(c[3])
        : "r"(a0), "r"(a1), "r"(a2), "r"(a3), "r"(b0), "r"(b1));
}

__device__ __forceinline__ void bsplit(float x, __nv_bfloat16& h, __nv_bfloat16& l) {
    h = __float2bfloat16(x);
    l = __float2bfloat16(x - __bfloat162float(h));
}

// ---------------- kernel 1: token-shift mix + bf16 split ----------
__global__ void mix_kernel(const float* __restrict__ x,
                           const float* __restrict__ mk,
                           const float* __restrict__ mv,
                           const float* __restrict__ mr) {
    int i = blockIdx.x * blockDim.x + threadIdx.x;   // float4 index
    int e = i * 4;
    int c   = e & (C - 1);
    int row = e >> 10;
    int t   = row & (T - 1);

    float4 xc = *(const float4*)(x + e);
    float4 xp = make_float4(0.f, 0.f, 0.f, 0.f);
    if (t > 0) xp = *(const float4*)(x + e - C);

    float4 a = *(const float4*)(mk + c);
    float4 b = *(const float4*)(mv + c);
    float4 d = *(const float4*)(mr + c);

    float xcv[4] = {xc.x, xc.y, xc.z, xc.w};
    float xpv[4] = {xp.x, xp.y, xp.z, xp.w};
    float mm[3][4] = {{a.x, a.y, a.z, a.w}, {b.x, b.y, b.z, b.w}, {d.x, d.y, d.z, d.w}};
    __nv_bfloat16* outh[3] = {g_xkh, g_xvh, g_xrh};
    __nv_bfloat16* outl[3] = {g_xkl, g_xvl, g_xrl};

#pragma unroll
    for (int m = 0; m < 3; m++) {
        __nv_bfloat16 h[4], lo[4];
#pragma unroll
        for (int j = 0; j < 4; j++) {
            float v = xcv[j] * mm[m][j] + xpv[j] * (1.f - mm[m][j]);
            bsplit(v, h[j], lo[j]);
        }
        *(__nv_bfloat162*)(outh[m] + e)     = __halves2bfloat162(h[0], h[1]);
        *(__nv_bfloat162*)(outh[m] + e + 2) = __halves2bfloat162(h[2], h[3]);
        *(__nv_bfloat162*)(outl[m] + e)     = __halves2bfloat162(lo[0], lo[1]);
        *(__nv_bfloat162*)(outl[m] + e + 2) = __halves2bfloat162(lo[2], lo[3]);
    }
}

// ---------------- kernel 2: weight bf16 split (all 4 weights) -----
__global__ void wsplit_kernel(const float* __restrict__ W0,
                              const float* __restrict__ W1,
                              const float* __restrict__ W2,
                              const float* __restrict__ W3) {
    int gi = blockIdx.x * blockDim.x + threadIdx.x;   // float4 index over 4*C*C
    int which = gi / (C * C / 4);
    int e = (gi - which * (C * C / 4)) * 4;
    const float* W = (which == 0) ? W0 : (which == 1) ? W1 : (which == 2) ? W2 : W3;
    __nv_bfloat16* Wh = g_Wh + (size_t)which * C * C;
    __nv_bfloat16* Wl = g_Wl + (size_t)which * C * C;

    float4 w = *(const float4*)(W + e);
    float wv[4] = {w.x, w.y, w.z, w.w};
    __nv_bfloat16 h[4], lo[4];
#pragma unroll
    for (int j = 0; j < 4; j++) bsplit(wv[j], h[j], lo[j]);
    *(__nv_bfloat162*)(Wh + e)     = __halves2bfloat162(h[0], h[1]);
    *(__nv_bfloat162*)(Wh + e + 2) = __halves2bfloat162(h[2], h[3]);
    *(__nv_bfloat162*)(Wl + e)     = __halves2bfloat162(lo[0], lo[1]);
    *(__nv_bfloat162*)(Wl + e + 2) = __halves2bfloat162(lo[2], lo[3]);
}

// ---------------- kernel 3: mma.sync split-bf16 GEMM --------------
// C[m][n] = sum_k A[m][k] * W[n][k], A/W as bf16 hi+lo splits.
// CTA tile 128x128, K-chunk 64, 8 warps (2x4), warp tile 64x32.
// Fragments loaded by direct LDS.32 (bank-conflict-free with 144B row stride).
constexpr int RSTRIDE    = 144;                      // 128B data + 16B pad
constexpr int ARR_BYTES  = 128 * RSTRIDE;            // 18432 per operand array
constexpr int STAGE_BYTES = 4 * ARR_BYTES;           // Ah,Al,Wh,Wl = 73728
constexpr int GEMM_SMEM  = 2 * STAGE_BYTES;          // 147456
constexpr int KSTAGES    = C / 64;                   // 16

template<int EPI>   // 0 = none, 1 = sigmoid
__global__ __launch_bounds__(256)
void gemm_mma(const __nv_bfloat16* __restrict__ Ah, const __nv_bfloat16* __restrict__ Al,
              const __nv_bfloat16* __restrict__ Bh, const __nv_bfloat16* __restrict__ Bl,
              float* __restrict__ Cout) {
    extern __shared__ __align__(16) char smem[];
    const uint32_t sbu = s2u(smem);
    const int tid  = threadIdx.x;
    const int wid  = tid >> 5, lane = tid & 31;
    const int g    = lane >> 2, tig = lane & 3;
    const int mw   = wid & 1, nw = wid >> 1;         // warp grid 2(m) x 4(n)
    const int bm   = blockIdx.y << 7, bn = blockIdx.x << 7;

    const __nv_bfloat16* gp[4] = {Ah, Al, Bh, Bl};
    const int rb[4] = {bm, bm, bn, bn};

    auto load_stage = [&](int s, int buf) {
        uint32_t st = sbu + buf * STAGE_BYTES;
#pragma unroll
        for (int a = 0; a < 4; a++) {
            uint32_t ab = st + a * ARR_BYTES;
            const __nv_bfloat16* gsrc = gp[a] + (size_t)rb[a] * C + s * 64;
#pragma unroll
            for (int i = tid; i < 1024; i += 256) {
                int row = i >> 3, cc = i & 7;
                uint32_t dst = ab + row * RSTRIDE + cc * 16;
                const void* src = gsrc + (size_t)row * C + cc * 8;
                asm volatile("cp.async.cg.shared.global [%0], [%1], 16;"
                             :: "r"(dst), "l"(src));
            }
        }
        asm volatile("cp.async.commit_group;" ::: "memory");
    };

    float acc[4][4][4];
#pragma unroll
    for (int i = 0; i < 4; i++)
#pragma unroll
        for (int j = 0; j < 4; j++)
#pragma unroll
            for (int r = 0; r < 4; r++) acc[i][j][r] = 0.f;

    // per-thread fragment base offsets (bytes within a stage)
    const int aoff = (mw * 64 + g) * RSTRIDE + tig * 4;   // A row m0+g, k byte tig*4
    const int boff = (nw * 32 + g) * RSTRIDE + tig * 4;   // W row n0+g

    load_stage(0, 0);

    for (int s = 0; s < KSTAGES; s++) {
        if (s + 1 < KSTAGES) {
            load_stage(s + 1, (s + 1) & 1);
            asm volatile("cp.async.wait_group 1;" ::: "memory");
        } else {
            asm volatile("cp.async.wait_group 0;" ::: "memory");
        }
        __syncthreads();

        const char* st = smem + (s & 1) * STAGE_BYTES;
        const char* pAh = st + aoff;
        const char* pAl = st + ARR_BYTES     + aoff;
        const char* pBh = st + 2 * ARR_BYTES + boff;
        const char* pBl = st + 3 * ARR_BYTES + boff;

#pragma unroll
        for (int kk = 0; kk < 4; kk++) {              // 4 k16 steps per chunk
            const int kb = kk * 32;                   // 16 bf16 = 32 bytes
            uint32_t ah[4][4], al[4][4], bh[4][2], bl[4][2];
#pragma unroll
            for (int i = 0; i < 4; i++) {             // a-frags: rows m0+i*16
                const int ro = i * (16 * RSTRIDE);
#pragma unroll
                for (int r = 0; r < 4; r++) {
                    const int o = ro + (r & 1) * (8 * RSTRIDE) + (r >> 1) * 16 + kb;
                    ah[i][r] = *(const uint32_t*)(pAh + o);
                    al[i][r] = *(const uint32_t*)(pAl + o);
                }
            }
#pragma unroll
            for (int j = 0; j < 4; j++) {             // b-frags: rows n0+j*8
                const int ro = j * (8 * RSTRIDE);
#pragma unroll
                for (int r = 0; r < 2; r++) {
                    const int o = ro + r * 16 + kb;
                    bh[j][r] = *(const uint32_t*)(pBh + o);
                    bl[j][r] = *(const uint32_t*)(pBl + o);
                }
            }
#pragma unroll
            for (int i = 0; i < 4; i++)
#pragma unroll
                for (int j = 0; j < 4; j++) {
                    mma_bf16(acc[i][j], ah[i][0], ah[i][1], ah[i][2], ah[i][3],
                             bh[j][0], bh[j][1]);
                    mma_bf16(acc[i][j], al[i][0], al[i][1], al[i][2], al[i][3],
                             bh[j][0], bh[j][1]);
                    mma_bf16(acc[i][j], ah[i][0], ah[i][1], ah[i][2], ah[i][3],
                             bl[j][0], bl[j][1]);
                }
        }
        __syncthreads();
    }

    // epilogue: c0,c1 -> (m0+g, n0+tig*2 .. +1); c2,c3 -> (m0+g+8, same cols)
#pragma unroll
    for (int i = 0; i < 4; i++) {
        int m0 = bm + mw * 64 + i * 16 + g;
#pragma unroll
        for (int j = 0; j < 4; j++) {
            int n0 = bn + nw * 32 + j * 8 + tig * 2;
            float o0 = acc[i][j][0], o1 = acc[i][j][1];
            float o2 = acc[i][j][2], o3 = acc[i][j][3];
            if (EPI == 1) {
                o0 = 1.f / (1.f + __expf(-o0)); o1 = 1.f / (1.f + __expf(-o1));
                o2 = 1.f / (1.f + __expf(-o2)); o3 = 1.f / (1.f + __expf(-o3));
            }
            *(float2*)(Cout + (size_t)m0 * C + n0)       = make_float2(o0, o1);
            *(float2*)(Cout + (size_t)(m0 + 8) * C + n0) = make_float2(o2, o3);
        }
    }
}

// ---------------- kernel 4: ek = exp(k) + row sums S --------------
__global__ void ekS_kernel() {
    int w    = (blockIdx.x * blockDim.x + threadIdx.x) >> 5;
    int lane = threadIdx.x & 31;
    int h  = w & (H - 1);
    int bt = w >> 4;
    size_t base = (size_t)bt * C + h * D + lane * 2;

    float2 kv = *(float2*)(g_k + base);
    float e0 = __expf(kv.x), e1 = __expf(kv.y);
    *(float2*)(g_k + base) = make_float2(e0, e1);

    float s = e0 + e1;
#pragma unroll
    for (int o = 16; o; o >>= 1) s += __shfl_xor_sync(0xffffffffu, s, o);
    if (lane == 0) {
        int b = bt >> 11;
        int t = bt & (T - 1);
        g_S[(size_t)(b * H + h) * T + t] = s;
    }
}

// ---------------- kernel 5: chunk scan pass 1 ---------------------
__global__ void scan1_kernel(const float* __restrict__ td) {
    int w    = (blockIdx.x * blockDim.x + threadIdx.x) >> 5;
    int lane = threadIdx.x & 31;
    int chunk = w & (NC - 1);
    int bh    = w >> 5;
    int h = bh & (H - 1);
    int b = bh >> 4;

    float ew = __expf(-__expf(td[h]));
    int t0 = chunk * L;
    size_t base = (size_t)(b * T + t0) * C + h * D + lane * 2;
    const float* Sp = g_S + (size_t)bh * T + t0;

    float sax = 0.f, say = 0.f, sb = 0.f;
#pragma unroll 4
    for (int s = 0; s < L; s++) {
        float2 e  = *(const float2*)(g_k + base);
        float2 vv = *(const float2*)(g_v + base);
        sax = ew * sax + e.x * vv.x;
        say = ew * say + e.y * vv.y;
        sb  = ew * sb  + Sp[s];
        base += C;
    }
    size_t ci = (size_t)w * D + lane * 2;
    g_cA[ci] = sax; g_cA[ci + 1] = say;
    if (lane == 0) g_cB[w] = sb;
}

// ---------------- kernel 6: sequential carry combine --------------
__global__ void combine_kernel(const float* __restrict__ td) {
    int bh   = blockIdx.x;
    int lane = threadIdx.x;
    int h = bh & (H - 1);
    float ewL = __expf(-(float)L * __expf(td[h]));

    float cax = 0.f, cay = 0.f, cb = 0.f;
    for (int c = 0; c < NC; c++) {
        size_t w  = (size_t)bh * NC + c;
        size_t ci = w * D + lane * 2;
        float Ax = g_cA[ci], Ay = g_cA[ci + 1];
        float Bc = g_cB[w];
        g_iA[ci] = cax; g_iA[ci + 1] = cay;
        if (lane == 0) g_iB[w] = cb;
        cax = ewL * cax + Ax;
        cay = ewL * cay + Ay;
        cb  = ewL * cb  + Bc;
    }
}

// ---------------- kernel 7: scan pass 2 (fused r*, bf16 split) ----
__global__ void scan3_kernel(const float* __restrict__ td,
                             const float* __restrict__ tf) {
    int w    = (blockIdx.x * blockDim.x + threadIdx.x) >> 5;
    int lane = threadIdx.x & 31;
    int chunk = w & (NC - 1);
    int bh    = w >> 5;
    int h = bh & (H - 1);
    int b = bh >> 4;

    float ew = __expf(-__expf(td[h]));
    float Eu = __expf(tf[h]);
    int t0 = chunk * L;
    size_t base = (size_t)(b * T + t0) * C + h * D + lane * 2;
    const float* Sp = g_S + (size_t)bh * T + t0;

    size_t ci = (size_t)w * D + lane * 2;
    float sax = g_iA[ci], say = g_iA[ci + 1];
    float sb  = g_iB[w];

#pragma unroll 4
    for (int s = 0; s < L; s++) {
        float2 e  = *(const float2*)(g_k + base);
        float2 vv = *(const float2*)(g_v + base);
        float2 r2 = *(const float2*)(g_r + base);
        float Sv = Sp[s];

        float den = sb + fmaxf(Eu * Sv, 1e-6f);
        float inv = 1.0f / den;
        float ox = r2.x * ((sax + Eu * e.x * vv.x) * inv);
        float oy = r2.y * ((say + Eu * e.y * vv.y) * inv);

        __nv_bfloat16 hx, lx, hy, ly;
        bsplit(ox, hx, lx); bsplit(oy, hy, ly);
        *(__nv_bfloat162*)(g_rwh + base) = __halves2bfloat162(hx, hy);
        *(__nv_bfloat162*)(g_rwl + base) = __halves2bfloat162(lx, ly);

        sax = ew * sax + e.x * vv.x;
        say = ew * say + e.y * vv.y;
        sb  = ew * sb  + Sv;
        base += C;
    }
}

// ---------------- launch ------------------------------------------
extern "C" void kernel_launch(void* const* d_in, const int* in_sizes, int n_in,
                              void* d_out, int out_size) {
    const float* x  = (const float*)d_in[0];
    const float* mk = (const float*)d_in[1];
    const float* mv = (const float*)d_in[2];
    const float* mr = (const float*)d_in[3];
    const float* Wk = (const float*)d_in[4];
    const float* Wv = (const float*)d_in[5];
    const float* Wr = (const float*)d_in[6];
    const float* Wo = (const float*)d_in[7];
    const float* td = (const float*)d_in[8];
    const float* tf = (const float*)d_in[9];
    float* out = (float*)d_out;

    __nv_bfloat16 *p_xkh, *p_xkl, *p_xvh, *p_xvl, *p_xrh, *p_xrl;
    __nv_bfloat16 *p_Wh, *p_Wl, *p_rwh, *p_rwl;
    float *p_k, *p_v, *p_r;
    cudaGetSymbolAddress((void**)&p_xkh, g_xkh);
    cudaGetSymbolAddress((void**)&p_xkl, g_xkl);
    cudaGetSymbolAddress((void**)&p_xvh, g_xvh);
    cudaGetSymbolAddress((void**)&p_xvl, g_xvl);
    cudaGetSymbolAddress((void**)&p_xrh, g_xrh);
    cudaGetSymbolAddress((void**)&p_xrl, g_xrl);
    cudaGetSymbolAddress((void**)&p_Wh,  g_Wh);
    cudaGetSymbolAddress((void**)&p_Wl,  g_Wl);
    cudaGetSymbolAddress((void**)&p_rwh, g_rwh);
    cudaGetSymbolAddress((void**)&p_rwl, g_rwl);
    cudaGetSymbolAddress((void**)&p_k,   g_k);
    cudaGetSymbolAddress((void**)&p_v,   g_v);
    cudaGetSymbolAddress((void**)&p_r,   g_r);

    cudaFuncSetAttribute(gemm_mma<0>, cudaFuncAttributeMaxDynamicSharedMemorySize, GEMM_SMEM);
    cudaFuncSetAttribute(gemm_mma<1>, cudaFuncAttributeMaxDynamicSharedMemorySize, GEMM_SMEM);

    // 1) token-shift mix -> bf16 splits
    mix_kernel<<<(BT * C / 4) / 256, 256>>>(x, mk, mv, mr);

    // 2) weight splits (single launch, all 4 weights)
    wsplit_kernel<<<(4 * C * C / 4) / 256, 256>>>(Wk, Wv, Wr, Wo);

    // 3) projections (split-bf16 via mma.sync)
    dim3 gg(C / 128, BT / 128);   // (8, 64)
    gemm_mma<0><<<gg, 256, GEMM_SMEM>>>(p_xkh, p_xkl, p_Wh, p_Wl, p_k);
    gemm_mma<0><<<gg, 256, GEMM_SMEM>>>(p_xvh, p_xvl, p_Wh + 1*(size_t)C*C, p_Wl + 1*(size_t)C*C, p_v);
    gemm_mma<1><<<gg, 256, GEMM_SMEM>>>(p_xrh, p_xrl, p_Wh + 2*(size_t)C*C, p_Wl + 2*(size_t)C*C, p_r);

    // 4) exp(k) + head row-sums
    ekS_kernel<<<(BT * H * 32) / 256, 256>>>();

    // 5-7) chunked linear scan (fused r*, writes bf16 split rwkv)
    scan1_kernel<<<(B * H * NC * 32) / 256, 256>>>(td);
    combine_kernel<<<B * H, 32>>>(td);
    scan3_kernel<<<(B * H * NC * 32) / 256, 256>>>(td, tf);

    // 8) output projection
    gemm_mma<0><<<gg, 256, GEMM_SMEM>>>(p_rwh, p_rwl, p_Wh + 3*(size_t)C*C, p_Wl + 3*(size_t)C*C, out);
}